// round 1
// baseline (speedup 1.0000x reference)
#include <cuda_runtime.h>
#include <math_constants.h>

// Problem constants (fixed by the reference: B=8, Te=Td=2048, D=256)
#define B_  8
#define T_  2048
#define D_  256
#define BQ  64
#define BK  64
#define NTHREADS 256

#define KS_STRIDE 260   // D + 4 floats padding (conflict-free transpose reads)
#define PS_STRIDE 68    // BK + 4

// smem layout (floats):
//   Qt [D_][BQ]          = 16384
//   Kt [D_][BK]          = 16384
//   Ks [BK][KS_STRIDE]   = 16640
//   Ps [BQ][PS_STRIDE]   =  4352
// total = 53760 floats = 215040 bytes (fits 227KB dynamic smem limit)
#define SMEM_FLOATS (D_*BQ + D_*BK + BK*KS_STRIDE + BQ*PS_STRIDE)

__global__ __launch_bounds__(NTHREADS, 1)
void luong_attn_kernel(const float* __restrict__ enc,
                       const float* __restrict__ dec,
                       float* __restrict__ out)
{
    extern __shared__ float sm[];
    float* Qt = sm;                         // [D_][BQ]   (q transposed: Qt[d][q])
    float* Kt = Qt + D_ * BQ;               // [D_][BK]   (k transposed: Kt[d][e])
    float* Ks = Kt + D_ * BK;               // [BK][KS_STRIDE] (k natural)
    float* Ps = Ks + BK * KS_STRIDE;        // [BQ][PS_STRIDE]

    const int b   = blockIdx.y;
    const int t0  = blockIdx.x * BQ;
    const int tid = threadIdx.x;
    const int ty  = tid >> 4;   // 0..15 -> owns q rows ty*4 .. ty*4+3
    const int tx  = tid & 15;   // 0..15 -> owns e cols tx*4.. (GEMM1), d cols {4tx+64j} (GEMM2)

    const float* encb = enc + (size_t)b * T_ * D_;
    const float* decb = dec + (size_t)b * T_ * D_;

    // ---------------- Load Q tile -> Qt (transposed), staged through Ks ----
    for (int idx = tid; idx < BQ * (D_ / 4); idx += NTHREADS) {
        int r  = idx / (D_ / 4);
        int c4 = idx % (D_ / 4);
        float4 v = reinterpret_cast<const float4*>(decb + (size_t)(t0 + r) * D_)[c4];
        *reinterpret_cast<float4*>(&Ks[r * KS_STRIDE + c4 * 4]) = v;
    }
    __syncthreads();
    {
        int rr = tid & 63;
        for (int c4 = tid >> 6; c4 < D_ / 4; c4 += 4) {
            float4 v = *reinterpret_cast<const float4*>(&Ks[rr * KS_STRIDE + c4 * 4]);
            Qt[(c4 * 4 + 0) * BQ + rr] = v.x;
            Qt[(c4 * 4 + 1) * BQ + rr] = v.y;
            Qt[(c4 * 4 + 2) * BQ + rr] = v.z;
            Qt[(c4 * 4 + 3) * BQ + rr] = v.w;
        }
    }
    __syncthreads();

    // ---------------- Flash accumulators ----------------------------------
    float m[4], l[4];
    float acc[4][16];
    #pragma unroll
    for (int i = 0; i < 4; i++) {
        m[i] = -CUDART_INF_F;
        l[i] = 0.0f;
        #pragma unroll
        for (int j = 0; j < 16; j++) acc[i][j] = 0.0f;
    }

    // ---------------- Main loop over encoder (key) blocks ------------------
    for (int e0 = 0; e0 < T_; e0 += BK) {
        // Load K tile: gmem (coalesced) -> Ks natural
        for (int idx = tid; idx < BK * (D_ / 4); idx += NTHREADS) {
            int r  = idx / (D_ / 4);
            int c4 = idx % (D_ / 4);
            float4 v = reinterpret_cast<const float4*>(encb + (size_t)(e0 + r) * D_)[c4];
            *reinterpret_cast<float4*>(&Ks[r * KS_STRIDE + c4 * 4]) = v;
        }
        __syncthreads();
        // Transpose Ks -> Kt (lanes along rows: conflict-free both sides)
        {
            int rr = tid & 63;
            for (int c4 = tid >> 6; c4 < D_ / 4; c4 += 4) {
                float4 v = *reinterpret_cast<const float4*>(&Ks[rr * KS_STRIDE + c4 * 4]);
                Kt[(c4 * 4 + 0) * BK + rr] = v.x;
                Kt[(c4 * 4 + 1) * BK + rr] = v.y;
                Kt[(c4 * 4 + 2) * BK + rr] = v.z;
                Kt[(c4 * 4 + 3) * BK + rr] = v.w;
            }
        }
        __syncthreads();

        // ---- GEMM1: S[4q][4e] = Q . K^T over d -------------------------
        float S[4][4];
        #pragma unroll
        for (int i = 0; i < 4; i++)
            #pragma unroll
            for (int j = 0; j < 4; j++) S[i][j] = 0.0f;

        #pragma unroll 8
        for (int d = 0; d < D_; d++) {
            float4 qv = *reinterpret_cast<const float4*>(&Qt[d * BQ + (ty << 2)]);
            float4 kv = *reinterpret_cast<const float4*>(&Kt[d * BK + (tx << 2)]);
            float q_[4] = {qv.x, qv.y, qv.z, qv.w};
            float k_[4] = {kv.x, kv.y, kv.z, kv.w};
            #pragma unroll
            for (int i = 0; i < 4; i++)
                #pragma unroll
                for (int j = 0; j < 4; j++)
                    S[i][j] = fmaf(q_[i], k_[j], S[i][j]);
        }

        // ---- Online softmax over this key block -------------------------
        #pragma unroll
        for (int i = 0; i < 4; i++) {
            float bm = fmaxf(fmaxf(S[i][0], S[i][1]), fmaxf(S[i][2], S[i][3]));
            #pragma unroll
            for (int off = 1; off < 16; off <<= 1)
                bm = fmaxf(bm, __shfl_xor_sync(0xffffffffu, bm, off));
            float newm  = fmaxf(m[i], bm);
            float alpha = __expf(m[i] - newm);   // 0 when m[i] == -inf

            float p0 = __expf(S[i][0] - newm);
            float p1 = __expf(S[i][1] - newm);
            float p2 = __expf(S[i][2] - newm);
            float p3 = __expf(S[i][3] - newm);
            float rs = (p0 + p1) + (p2 + p3);
            #pragma unroll
            for (int off = 1; off < 16; off <<= 1)
                rs += __shfl_xor_sync(0xffffffffu, rs, off);

            l[i] = l[i] * alpha + rs;
            m[i] = newm;
            #pragma unroll
            for (int j = 0; j < 16; j++) acc[i][j] *= alpha;

            float4 pv = make_float4(p0, p1, p2, p3);
            *reinterpret_cast<float4*>(&Ps[((ty << 2) + i) * PS_STRIDE + (tx << 2)]) = pv;
        }
        __syncthreads();

        // ---- GEMM2: acc[4q][16d] += P[q][e] * K[e][d] --------------------
        #pragma unroll 2
        for (int e = 0; e < BK; e++) {
            float p0 = Ps[((ty << 2) + 0) * PS_STRIDE + e];
            float p1 = Ps[((ty << 2) + 1) * PS_STRIDE + e];
            float p2 = Ps[((ty << 2) + 2) * PS_STRIDE + e];
            float p3 = Ps[((ty << 2) + 3) * PS_STRIDE + e];
            #pragma unroll
            for (int j = 0; j < 4; j++) {
                float4 kv = *reinterpret_cast<const float4*>(
                    &Ks[e * KS_STRIDE + (tx << 2) + (j << 6)]);
                acc[0][j * 4 + 0] = fmaf(p0, kv.x, acc[0][j * 4 + 0]);
                acc[0][j * 4 + 1] = fmaf(p0, kv.y, acc[0][j * 4 + 1]);
                acc[0][j * 4 + 2] = fmaf(p0, kv.z, acc[0][j * 4 + 2]);
                acc[0][j * 4 + 3] = fmaf(p0, kv.w, acc[0][j * 4 + 3]);
                acc[1][j * 4 + 0] = fmaf(p1, kv.x, acc[1][j * 4 + 0]);
                acc[1][j * 4 + 1] = fmaf(p1, kv.y, acc[1][j * 4 + 1]);
                acc[1][j * 4 + 2] = fmaf(p1, kv.z, acc[1][j * 4 + 2]);
                acc[1][j * 4 + 3] = fmaf(p1, kv.w, acc[1][j * 4 + 3]);
                acc[2][j * 4 + 0] = fmaf(p2, kv.x, acc[2][j * 4 + 0]);
                acc[2][j * 4 + 1] = fmaf(p2, kv.y, acc[2][j * 4 + 1]);
                acc[2][j * 4 + 2] = fmaf(p2, kv.z, acc[2][j * 4 + 2]);
                acc[2][j * 4 + 3] = fmaf(p2, kv.w, acc[2][j * 4 + 3]);
                acc[3][j * 4 + 0] = fmaf(p3, kv.x, acc[3][j * 4 + 0]);
                acc[3][j * 4 + 1] = fmaf(p3, kv.y, acc[3][j * 4 + 1]);
                acc[3][j * 4 + 2] = fmaf(p3, kv.z, acc[3][j * 4 + 2]);
                acc[3][j * 4 + 3] = fmaf(p3, kv.w, acc[3][j * 4 + 3]);
            }
        }
        __syncthreads();   // before next iteration overwrites Ks/Kt
    }

    // ---------------- Epilogue: out = [dec | acc / l] ----------------------
    #pragma unroll
    for (int i = 0; i < 4; i++) {
        float inv = 1.0f / l[i];
        size_t row = ((size_t)b * T_ + t0 + (ty << 2) + i) * (2 * D_);
        #pragma unroll
        for (int j = 0; j < 4; j++) {
            float4 v = make_float4(acc[i][j * 4 + 0] * inv,
                                   acc[i][j * 4 + 1] * inv,
                                   acc[i][j * 4 + 2] * inv,
                                   acc[i][j * 4 + 3] * inv);
            *reinterpret_cast<float4*>(&out[row + D_ + (tx << 2) + (j << 6)]) = v;
        }
    }
    // copy decoder rows into out[..., 0:256]
    for (int idx = tid; idx < BQ * (D_ / 4); idx += NTHREADS) {
        int r  = idx / (D_ / 4);
        int c4 = idx % (D_ / 4);
        float4 v = reinterpret_cast<const float4*>(decb + (size_t)(t0 + r) * D_)[c4];
        *reinterpret_cast<float4*>(&out[((size_t)b * T_ + t0 + r) * (2 * D_) + c4 * 4]) = v;
    }
}

extern "C" void kernel_launch(void* const* d_in, const int* in_sizes, int n_in,
                              void* d_out, int out_size)
{
    const float* enc = (const float*)d_in[0];  // encoder_outputs [8,2048,256]
    const float* dec = (const float*)d_in[1];  // decoder_outputs [8,2048,256]
    float* out = (float*)d_out;                // [8,2048,512]

    (void)in_sizes; (void)n_in; (void)out_size;

    static_assert(SMEM_FLOATS * sizeof(float) <= 232448, "smem over limit");
    cudaFuncSetAttribute(luong_attn_kernel,
                         cudaFuncAttributeMaxDynamicSharedMemorySize,
                         SMEM_FLOATS * (int)sizeof(float));

    dim3 grid(T_ / BQ, B_);
    luong_attn_kernel<<<grid, NTHREADS, SMEM_FLOATS * sizeof(float)>>>(enc, dec, out);
}